// round 5
// baseline (speedup 1.0000x reference)
#include <cuda_runtime.h>
#include <cuda_bf16.h>

// KernelApply: out[b,c,h,w] = sum_{i,j} softmax_t(kernels[b,:,h,w])[i*5+j] * data[b,c,h+i-2,w+j-2]
// (out-of-range taps contribute 0; softmax denominator over all 25 taps regardless)
//
// Key identity: out = (sum_t exp(k_t) * tap_t) / (sum_t exp(k_t))
//   -> stream kernels once, never materialize normalized weights.
//
// Thread layout: 1 thread = 4 consecutive output pixels (float4 on W), all 3 channels.
//   - 25x LDG.128 for kernel weights (coalesced 512B/warp per tap)
//   - per (channel, row): LDG.64 + LDG.128 + LDG.64 covering the 8-float window
//     [w4-2 .. w4+5]; all naturally aligned since w4 % 4 == 0.
// HBM-bound: ~457 MB total DRAM traffic (kernels 369 + data 44 + out 44).

namespace {

constexpr int B = 4, C = 3, H = 720, W = 1280, K = 5;
constexpr int HW = H * W;
constexpr int W4 = W / 4;
constexpr int NTHREADS = B * H * W4;   // 921,600
constexpr int BLOCK = 256;

__global__ void __launch_bounds__(BLOCK)
kw_kernel(const float* __restrict__ data,
          const float* __restrict__ kern,
          float* __restrict__ out)
{
    int idx = blockIdx.x * BLOCK + threadIdx.x;
    if (idx >= NTHREADS) return;

    int w4 = (idx % W4) * 4;
    int t  = idx / W4;
    int h  = t % H;
    int b  = t / H;

    const float* kp = kern + ((b * 25) * H + h) * W + w4;   // + tap*HW per tap
    const float* db = data + b * C * HW;

    float acc[3][4] = {};
    float sw[4]     = {};

    #pragma unroll
    for (int i = 0; i < K; i++) {
        int hh = h + i - 2;
        bool vr = ((unsigned)hh < (unsigned)H);

        // Sliding window registers: r[c][q] = data[b,c,hh, w4-2+q], q in [0,8)
        float r[3][8];
        #pragma unroll
        for (int c = 0; c < 3; c++) {
            float2 L = make_float2(0.f, 0.f);
            float4 M = make_float4(0.f, 0.f, 0.f, 0.f);
            float2 R = make_float2(0.f, 0.f);
            if (vr) {
                const float* row = db + (c * H + hh) * W;
                if (w4 >= 2)     L = *reinterpret_cast<const float2*>(row + w4 - 2);
                M = *reinterpret_cast<const float4*>(row + w4);
                if (w4 + 4 < W)  R = *reinterpret_cast<const float2*>(row + w4 + 4);
            }
            r[c][0] = L.x; r[c][1] = L.y;
            r[c][2] = M.x; r[c][3] = M.y; r[c][4] = M.z; r[c][5] = M.w;
            r[c][6] = R.x; r[c][7] = R.y;
        }

        #pragma unroll
        for (int j = 0; j < K; j++) {
            float4 kv = *reinterpret_cast<const float4*>(kp + (i * 5 + j) * HW);
            float e0 = __expf(kv.x);
            float e1 = __expf(kv.y);
            float e2 = __expf(kv.z);
            float e3 = __expf(kv.w);
            sw[0] += e0; sw[1] += e1; sw[2] += e2; sw[3] += e3;
            // pixel p (p=0..3) at tap j reads column offset (j-2+p) -> r index j+p
            #pragma unroll
            for (int c = 0; c < 3; c++) {
                acc[c][0] = fmaf(e0, r[c][j + 0], acc[c][0]);
                acc[c][1] = fmaf(e1, r[c][j + 1], acc[c][1]);
                acc[c][2] = fmaf(e2, r[c][j + 2], acc[c][2]);
                acc[c][3] = fmaf(e3, r[c][j + 3], acc[c][3]);
            }
        }
    }

    float inv0 = __fdividef(1.f, sw[0]);
    float inv1 = __fdividef(1.f, sw[1]);
    float inv2 = __fdividef(1.f, sw[2]);
    float inv3 = __fdividef(1.f, sw[3]);

    float* ob = out + ((b * C) * H + h) * W + w4;
    #pragma unroll
    for (int c = 0; c < 3; c++) {
        float4 o;
        o.x = acc[c][0] * inv0;
        o.y = acc[c][1] * inv1;
        o.z = acc[c][2] * inv2;
        o.w = acc[c][3] * inv3;
        *reinterpret_cast<float4*>(ob + c * HW) = o;
    }
}

} // namespace

extern "C" void kernel_launch(void* const* d_in, const int* in_sizes, int n_in,
                              void* d_out, int out_size)
{
    const float* data = (const float*)d_in[0];   // [B, C, H, W]
    const float* kern = (const float*)d_in[1];   // [B, 25, H, W]
    float* out        = (float*)d_out;           // [B, C, H, W]

    int blocks = (NTHREADS + BLOCK - 1) / BLOCK;
    kw_kernel<<<blocks, BLOCK>>>(data, kern, out);
}

// round 9
// speedup vs baseline: 1.0518x; 1.0518x over previous
#include <cuda_runtime.h>
#include <cuda_bf16.h>

// KernelApply: out[b,c,h,w] = sum_{i,j} softmax_t(kernels[b,:,h,w])[i*5+j] * data[b,c,h+i-2,w+j-2]
// Identity: out = (sum_t exp(k_t) * tap_t) / (sum_t exp(k_t)) -> single streaming pass.
//
// R5 changes (occupancy push):
//  - Register restructure: per row i, compute all 20 exp-weights FIRST, then
//    consume the 8-wide data window one channel at a time (peak live ~54 regs).
//  - __launch_bounds__(256, 4): force <=64 regs -> 4 blocks/SM (1024 thr, 50% occ).
//  - __ldcs on kernel stream (369 MB read-once): evict-first, protects the
//    44 MB data working set in L2 (data row reuse is L2-served; DRAM ~457 MB floor).

namespace {

constexpr int B = 4, C = 3, H = 720, W = 1280, K = 5;
constexpr int HW = H * W;
constexpr int W4 = W / 4;
constexpr int NTHREADS = B * H * W4;   // 921,600
constexpr int BLOCK = 256;

__global__ void __launch_bounds__(BLOCK, 4)
kw_kernel(const float* __restrict__ data,
          const float* __restrict__ kern,
          float* __restrict__ out)
{
    int idx = blockIdx.x * BLOCK + threadIdx.x;

    int w4 = (idx % W4) * 4;
    int t  = idx / W4;
    int h  = t % H;
    int b  = t / H;

    const float* kp = kern + ((b * 25) * H + h) * W + w4;   // + tap*HW per tap
    const float* db = data + b * C * HW;

    const bool okL = (w4 >= 2);
    const bool okR = (w4 + 4 < W);

    float acc[3][4] = {};
    float sw[4]     = {};

    #pragma unroll
    for (int i = 0; i < K; i++) {
        int hh = h + i - 2;
        bool vr = ((unsigned)hh < (unsigned)H);

        // ---- Phase 1: all 5 taps of this row -> 20 exp-weights (batched LDG.128, streaming) ----
        float e[5][4];
        #pragma unroll
        for (int j = 0; j < K; j++) {
            float4 kv = __ldcs(reinterpret_cast<const float4*>(kp + (i * 5 + j) * HW));
            e[j][0] = __expf(kv.x);
            e[j][1] = __expf(kv.y);
            e[j][2] = __expf(kv.z);
            e[j][3] = __expf(kv.w);
            sw[0] += e[j][0];
            sw[1] += e[j][1];
            sw[2] += e[j][2];
            sw[3] += e[j][3];
        }

        // ---- Phase 2: per channel, load 8-wide window and consume immediately ----
        #pragma unroll
        for (int c = 0; c < 3; c++) {
            float2 Lv = make_float2(0.f, 0.f);
            float4 Mv = make_float4(0.f, 0.f, 0.f, 0.f);
            float2 Rv = make_float2(0.f, 0.f);
            if (vr) {
                const float* row = db + (c * H + hh) * W;
                if (okL) Lv = *reinterpret_cast<const float2*>(row + w4 - 2);
                Mv = *reinterpret_cast<const float4*>(row + w4);
                if (okR) Rv = *reinterpret_cast<const float2*>(row + w4 + 4);
            }
            float r[8];
            r[0] = Lv.x; r[1] = Lv.y;
            r[2] = Mv.x; r[3] = Mv.y; r[4] = Mv.z; r[5] = Mv.w;
            r[6] = Rv.x; r[7] = Rv.y;

            #pragma unroll
            for (int j = 0; j < K; j++) {
                acc[c][0] = fmaf(e[j][0], r[j + 0], acc[c][0]);
                acc[c][1] = fmaf(e[j][1], r[j + 1], acc[c][1]);
                acc[c][2] = fmaf(e[j][2], r[j + 2], acc[c][2]);
                acc[c][3] = fmaf(e[j][3], r[j + 3], acc[c][3]);
            }
        }
    }

    float inv0 = __fdividef(1.f, sw[0]);
    float inv1 = __fdividef(1.f, sw[1]);
    float inv2 = __fdividef(1.f, sw[2]);
    float inv3 = __fdividef(1.f, sw[3]);

    float* ob = out + ((b * C) * H + h) * W + w4;
    #pragma unroll
    for (int c = 0; c < 3; c++) {
        float4 o;
        o.x = acc[c][0] * inv0;
        o.y = acc[c][1] * inv1;
        o.z = acc[c][2] * inv2;
        o.w = acc[c][3] * inv3;
        *reinterpret_cast<float4*>(ob + c * HW) = o;
    }
}

} // namespace

extern "C" void kernel_launch(void* const* d_in, const int* in_sizes, int n_in,
                              void* d_out, int out_size)
{
    const float* data = (const float*)d_in[0];   // [B, C, H, W]
    const float* kern = (const float*)d_in[1];   // [B, 25, H, W]
    float* out        = (float*)d_out;           // [B, C, H, W]

    int blocks = NTHREADS / BLOCK;               // exact: 921600 / 256 = 3600
    kw_kernel<<<blocks, BLOCK>>>(data, kern, out);
}